// round 6
// baseline (speedup 1.0000x reference)
#include <cuda_runtime.h>
#include <math.h>

#define TT 50
#define BB 256
#define DBEL 1024
#define DST 128
#define DACT 32
#define DHID 1024
#define DEMB 1024
#define GRU3 (3*DBEL)

// ---- output layout (tuple order: beliefs, prior_s, mp, sp, post_s, mq, sq) ----
static constexpr size_t OFF_BEL = 0;
static constexpr size_t OFF_PRS = (size_t)TT*BB*DBEL;
static constexpr size_t OFF_MP  = OFF_PRS + (size_t)TT*BB*DST;
static constexpr size_t OFF_SP  = OFF_MP  + (size_t)TT*BB*DST;
static constexpr size_t OFF_POS = OFF_SP  + (size_t)TT*BB*DST;
static constexpr size_t OFF_MQ  = OFF_POS + (size_t)TT*BB*DST;
static constexpr size_t OFF_SQ  = OFF_MQ  + (size_t)TT*BB*DST;

// ---- scratch (device globals; no allocation allowed) ----
__device__ float g_x[BB*DBEL];
__device__ float g_gi[BB*GRU3];
__device__ float g_gh[BB*GRU3];
__device__ float g_belief[BB*DBEL];
__device__ float g_hq[BB*DHID];                 // pre-activation (bias-seeded, atomic-accumulated)
__device__ float g_hp[(size_t)TT*BB*DHID];      // batched prior hidden (52 MB)

__device__ __forceinline__ float eluf(float x)   { return x > 0.f ? x : expm1f(x); }
__device__ __forceinline__ float splusf(float x) { return fmaxf(x, 0.f) + log1pf(expf(-fabsf(x))); }
__device__ __forceinline__ float sigf(float x)   { return 1.f / (1.f + expf(-x)); }

// ---- flexible GEMM: C[M,N] = epi(Aload(A) @ W^T + bias), W is [N,K] row-major ----
enum { ALOAD_PLAIN = 0, ALOAD_ELU = 1, ALOAD_STATE = 2 };
enum { EPI_BIAS = 0, EPI_BIAS_ELU = 1, EPI_ATOMIC = 2, EPI_HEAD_ATOMIC = 3, EPI_HEAD_STORE = 4 };

struct GemmJob {
    const float* A1; int lda1;
    const float* A2; int lda2;     // second concat segment (cols >= K1)
    int K1; int K;
    const float* W;                // [N, K] row-major (ldw == K)
    const float* bias;
    float* out; int ldout;
    float* mean_out; float* std_out;   // head epilogues
    const float* st_mq; const float* st_sq; const float* st_eps;
    const float* st_nt; const float* st_prev;   // fused-state loader
    int aload; int epi;
};
struct GemmLaunch { GemmJob job[2]; int mblk; int splitk; };

__device__ __forceinline__ void load_a8(const GemmJob& jb, int gm, int k, float* r)
{
    if (jb.aload == ALOAD_STATE && k < jb.K1) {
        const float nt = jb.st_nt[gm];
        const int base = gm * DST + k;
        if (jb.st_mq) {
#pragma unroll
            for (int i = 0; i < 8; i++) {
                float s = splusf(jb.st_sq[base + i]) + 0.1f;
                r[i] = (jb.st_mq[base + i] + s * jb.st_eps[base + i]) * nt;
            }
        } else {
#pragma unroll
            for (int i = 0; i < 8; i++) r[i] = jb.st_prev[base + i] * nt;
        }
        return;
    }
    const float* p;
    if (k < jb.K1) p = jb.A1 + (size_t)gm * jb.lda1 + k;
    else           p = jb.A2 + (size_t)gm * jb.lda2 + (k - jb.K1);
    float4 v0 = *reinterpret_cast<const float4*>(p);
    float4 v1 = *reinterpret_cast<const float4*>(p + 4);
    r[0] = v0.x; r[1] = v0.y; r[2] = v0.z; r[3] = v0.w;
    r[4] = v1.x; r[5] = v1.y; r[6] = v1.z; r[7] = v1.w;
    if (jb.aload == ALOAD_ELU) {
#pragma unroll
        for (int i = 0; i < 8; i++) r[i] = eluf(r[i]);
    }
}

__device__ __forceinline__ void load_b8(const GemmJob& jb, int gn, int k, float* r)
{
    const float* p = jb.W + (size_t)gn * jb.K + k;
    float4 v0 = *reinterpret_cast<const float4*>(p);
    float4 v1 = *reinterpret_cast<const float4*>(p + 4);
    r[0] = v0.x; r[1] = v0.y; r[2] = v0.z; r[3] = v0.w;
    r[4] = v1.x; r[5] = v1.y; r[6] = v1.z; r[7] = v1.w;
}

__global__ void __launch_bounds__(256) gemm_kernel(GemmLaunch P)
{
    const GemmJob jb = P.job[blockIdx.z];
    const int mb = blockIdx.y % P.mblk;
    const int kc = blockIdx.y / P.mblk;
    const int nb = blockIdx.x;
    const int Kc = jb.K / P.splitk;
    const int kbeg = kc * Kc;
    const int ntile = Kc >> 5;

    __shared__ __align__(16) float As[32][68];
    __shared__ __align__(16) float Bs[32][68];

    const int tid  = threadIdx.x;
    const int lrow = tid >> 2;          // 0..63
    const int lk   = (tid & 3) << 3;    // 0,8,16,24
    const int gm   = mb * 64 + lrow;
    const int gn   = nb * 64 + lrow;
    const int tx   = tid & 15;
    const int ty   = tid >> 4;

    float ra[8], rb[8];
    load_a8(jb, gm, kbeg + lk, ra);          // FIX: + lk
    load_b8(jb, gn, kbeg + lk, rb);          // FIX: + lk
#pragma unroll
    for (int i = 0; i < 8; i++) { As[lk + i][lrow] = ra[i]; Bs[lk + i][lrow] = rb[i]; }
    __syncthreads();

    float acc[16];
#pragma unroll
    for (int i = 0; i < 16; i++) acc[i] = 0.f;

    for (int t = 0; t < ntile; t++) {
        const bool more = (t + 1 < ntile);
        if (more) {
            load_a8(jb, gm, kbeg + (t + 1) * 32 + lk, ra);   // FIX: + lk
            load_b8(jb, gn, kbeg + (t + 1) * 32 + lk, rb);   // FIX: + lk
        }
#pragma unroll
        for (int k = 0; k < 32; k++) {
            float4 a = *reinterpret_cast<const float4*>(&As[k][ty << 2]);
            float4 b = *reinterpret_cast<const float4*>(&Bs[k][tx << 2]);
            acc[0]  += a.x * b.x; acc[1]  += a.x * b.y; acc[2]  += a.x * b.z; acc[3]  += a.x * b.w;
            acc[4]  += a.y * b.x; acc[5]  += a.y * b.y; acc[6]  += a.y * b.z; acc[7]  += a.y * b.w;
            acc[8]  += a.z * b.x; acc[9]  += a.z * b.y; acc[10] += a.z * b.z; acc[11] += a.z * b.w;
            acc[12] += a.w * b.x; acc[13] += a.w * b.y; acc[14] += a.w * b.z; acc[15] += a.w * b.w;
        }
        __syncthreads();
        if (more) {
#pragma unroll
            for (int i = 0; i < 8; i++) { As[lk + i][lrow] = ra[i]; Bs[lk + i][lrow] = rb[i]; }
            __syncthreads();
        }
    }

    const int m0 = mb * 64 + (ty << 2);
    const int n0 = nb * 64 + (tx << 2);

    if (jb.epi == EPI_BIAS) {
#pragma unroll
        for (int i = 0; i < 4; i++) {
            float* o = jb.out + (size_t)(m0 + i) * jb.ldout + n0;
#pragma unroll
            for (int j = 0; j < 4; j++) o[j] = acc[i * 4 + j] + jb.bias[n0 + j];
        }
    } else if (jb.epi == EPI_BIAS_ELU) {
#pragma unroll
        for (int i = 0; i < 4; i++) {
            float* o = jb.out + (size_t)(m0 + i) * jb.ldout + n0;
#pragma unroll
            for (int j = 0; j < 4; j++) o[j] = eluf(acc[i * 4 + j] + jb.bias[n0 + j]);
        }
    } else if (jb.epi == EPI_ATOMIC) {
#pragma unroll
        for (int i = 0; i < 4; i++) {
            float* o = jb.out + (size_t)(m0 + i) * jb.ldout + n0;
#pragma unroll
            for (int j = 0; j < 4; j++) atomicAdd(o + j, acc[i * 4 + j]);
        }
    } else if (jb.epi == EPI_HEAD_ATOMIC) {
#pragma unroll
        for (int i = 0; i < 4; i++) {
#pragma unroll
            for (int j = 0; j < 4; j++) {
                int n = n0 + j;
                float v = acc[i * 4 + j] + (kc == 0 ? jb.bias[n] : 0.f);
                if (n < DST) atomicAdd(jb.mean_out + (size_t)(m0 + i) * DST + n, v);
                else         atomicAdd(jb.std_out  + (size_t)(m0 + i) * DST + (n - DST), v);
            }
        }
    } else { // EPI_HEAD_STORE
#pragma unroll
        for (int i = 0; i < 4; i++) {
#pragma unroll
            for (int j = 0; j < 4; j++) {
                int n = n0 + j;
                float v = acc[i * 4 + j] + jb.bias[n];
                if (n < DST) jb.mean_out[(size_t)(m0 + i) * DST + n] = v;
                else         jb.std_out[(size_t)(m0 + i) * DST + (n - DST)] = splusf(v) + 0.1f;
            }
        }
    }
}

// ---- GRU combine: h = (1-z)*n + z*belief; also seeds g_hq with b_poh ----
__global__ void gru_kernel(const float* __restrict__ b_poh, float* __restrict__ bel_out)
{
    int idx = blockIdx.x * 256 + threadIdx.x;    // BB*DBEL threads
    int m = idx >> 10, j = idx & 1023;
    const float* gi = g_gi + (size_t)m * GRU3;
    const float* gh = g_gh + (size_t)m * GRU3;
    float r = sigf(gi[j] + gh[j]);
    float z = sigf(gi[j + 1024] + gh[j + 1024]);
    float n = tanhf(gi[j + 2048] + r * gh[j + 2048]);
    float b = g_belief[idx];
    float h = (1.f - z) * n + z * b;
    g_belief[idx] = h;
    bel_out[idx]  = h;
    g_hq[idx] = b_poh[j];   // pre-seed bias for split-K atomic hq GEMM
}

// ---- init: copy prev_belief into scratch; zero mq/sq atomic regions of d_out ----
__global__ void init_kernel(const float* __restrict__ prev_belief, float* __restrict__ out)
{
    int idx = blockIdx.x * 256 + threadIdx.x;
    if (idx < BB * DBEL) g_belief[idx] = prev_belief[idx];
    if (idx < 2 * TT * BB * DST) out[OFF_MQ + idx] = 0.f;
}

// ---- final: finish sq (softplus), produce prior/posterior samples for all T ----
__global__ void sample_kernel(float* __restrict__ out,
                              const float* __restrict__ ep, const float* __restrict__ eq)
{
    size_t idx = (size_t)blockIdx.x * 256 + threadIdx.x;
    if (idx >= (size_t)TT * BB * DST) return;
    out[OFF_PRS + idx] = out[OFF_MP + idx] + out[OFF_SP + idx] * ep[idx];
    float s = splusf(out[OFF_SQ + idx]) + 0.1f;
    out[OFF_SQ + idx]  = s;
    out[OFF_POS + idx] = out[OFF_MQ + idx] + s * eq[idx];
}

extern "C" void kernel_launch(void* const* d_in, const int* in_sizes, int n_in,
                              void* d_out, int out_size)
{
    (void)in_sizes; (void)n_in; (void)out_size;
    const float* prev_state   = (const float*)d_in[0];
    const float* actions      = (const float*)d_in[1];
    const float* prev_belief  = (const float*)d_in[2];
    const float* observations = (const float*)d_in[3];
    const float* nonterminals = (const float*)d_in[4];
    const float* prior_noise  = (const float*)d_in[5];
    const float* post_noise   = (const float*)d_in[6];
    const float* W_sa  = (const float*)d_in[7];
    const float* b_sa  = (const float*)d_in[8];
    const float* w_ih  = (const float*)d_in[9];
    const float* b_ih  = (const float*)d_in[10];
    const float* w_hh  = (const float*)d_in[11];
    const float* b_hh  = (const float*)d_in[12];
    const float* W_prh = (const float*)d_in[13];
    const float* b_prh = (const float*)d_in[14];
    const float* W_prs = (const float*)d_in[15];
    const float* b_prs = (const float*)d_in[16];
    const float* W_poh = (const float*)d_in[17];
    const float* b_poh = (const float*)d_in[18];
    const float* W_pos = (const float*)d_in[19];
    const float* b_pos = (const float*)d_in[20];
    float* out = (float*)d_out;

    float *px, *pgi, *pgh, *pbel, *phq, *php;
    cudaGetSymbolAddress((void**)&px,   g_x);
    cudaGetSymbolAddress((void**)&pgi,  g_gi);
    cudaGetSymbolAddress((void**)&pgh,  g_gh);
    cudaGetSymbolAddress((void**)&pbel, g_belief);
    cudaGetSymbolAddress((void**)&phq,  g_hq);
    cudaGetSymbolAddress((void**)&php,  g_hp);

    init_kernel<<<(2 * TT * BB * DST + 255) / 256, 256>>>(prev_belief, out);

    for (int t = 0; t < TT; t++) {
        // 1) x = elu([state*nt, a_t] @ W_sa^T + b_sa); state fused from prev mq/sq/eps
        {
            GemmLaunch L = {};
            GemmJob& j = L.job[0];
            j.A2 = actions + (size_t)t * BB * DACT; j.lda2 = DACT;
            j.K1 = DST; j.K = DST + DACT;
            j.W = W_sa; j.bias = b_sa;
            j.out = px; j.ldout = DBEL;
            j.st_nt = nonterminals + (size_t)t * BB;
            if (t == 0) {
                j.st_prev = prev_state; j.st_mq = nullptr;
            } else {
                j.st_mq  = out + OFF_MQ + (size_t)(t - 1) * BB * DST;
                j.st_sq  = out + OFF_SQ + (size_t)(t - 1) * BB * DST;
                j.st_eps = post_noise + (size_t)(t - 1) * BB * DST;
            }
            j.aload = ALOAD_STATE; j.epi = EPI_BIAS_ELU;
            L.mblk = 4; L.splitk = 1;
            gemm_kernel<<<dim3(DBEL / 64, 4, 1), 256>>>(L);
        }
        // 2) gi = x @ w_ih^T + b_ih ; gh = belief @ w_hh^T + b_hh  (two jobs, one launch)
        {
            GemmLaunch L = {};
            GemmJob& a = L.job[0];
            a.A1 = px; a.lda1 = DBEL; a.K1 = DBEL; a.K = DBEL;
            a.W = w_ih; a.bias = b_ih; a.out = pgi; a.ldout = GRU3;
            a.aload = ALOAD_PLAIN; a.epi = EPI_BIAS;
            GemmJob& b = L.job[1];
            b.A1 = pbel; b.lda1 = DBEL; b.K1 = DBEL; b.K = DBEL;
            b.W = w_hh; b.bias = b_hh; b.out = pgh; b.ldout = GRU3;
            b.aload = ALOAD_PLAIN; b.epi = EPI_BIAS;
            L.mblk = 4; L.splitk = 1;
            gemm_kernel<<<dim3(GRU3 / 64, 4, 2), 256>>>(L);
        }
        // 3) GRU combine -> h (updates g_belief in place, writes beliefs output, seeds g_hq)
        gru_kernel<<<BB * DBEL / 256, 256>>>(b_poh, out + OFF_BEL + (size_t)t * BB * DBEL);
        // 4) hq_raw += [h, obs_t] @ W_poh^T  (split-K=2, atomic; bias pre-seeded)
        {
            GemmLaunch L = {};
            GemmJob& j = L.job[0];
            j.A1 = pbel; j.lda1 = DBEL; j.K1 = DBEL;
            j.A2 = observations + (size_t)t * BB * DEMB; j.lda2 = DEMB;
            j.K = DBEL + DEMB;
            j.W = W_poh; j.out = phq; j.ldout = DHID;
            j.aload = ALOAD_PLAIN; j.epi = EPI_ATOMIC;
            L.mblk = 4; L.splitk = 2;
            gemm_kernel<<<dim3(DHID / 64, 4 * 2, 1), 256>>>(L);
        }
        // 5) posterior head: elu(hq_raw) @ W_pos^T + b_pos -> mq (final), sq (raw) in d_out
        {
            GemmLaunch L = {};
            GemmJob& j = L.job[0];
            j.A1 = phq; j.lda1 = DHID; j.K1 = DHID; j.K = DHID;
            j.W = W_pos; j.bias = b_pos;
            j.mean_out = out + OFF_MQ + (size_t)t * BB * DST;
            j.std_out  = out + OFF_SQ + (size_t)t * BB * DST;
            j.aload = ALOAD_ELU; j.epi = EPI_HEAD_ATOMIC;
            L.mblk = 4; L.splitk = 8;
            gemm_kernel<<<dim3(2 * DST / 64, 4 * 8, 1), 256>>>(L);
        }
    }

    // 6) batched prior hidden over all T: hp = elu(beliefs @ W_prh^T + b_prh), M = 12800
    {
        GemmLaunch L = {};
        GemmJob& j = L.job[0];
        j.A1 = out + OFF_BEL; j.lda1 = DBEL; j.K1 = DBEL; j.K = DBEL;
        j.W = W_prh; j.bias = b_prh; j.out = php; j.ldout = DHID;
        j.aload = ALOAD_PLAIN; j.epi = EPI_BIAS_ELU;
        L.mblk = TT * BB / 64; L.splitk = 1;
        gemm_kernel<<<dim3(DHID / 64, TT * BB / 64, 1), 256>>>(L);
    }
    // 7) batched prior head: hp @ W_prs^T + b_prs -> mp, sp(=softplus+0.1)
    {
        GemmLaunch L = {};
        GemmJob& j = L.job[0];
        j.A1 = php; j.lda1 = DHID; j.K1 = DHID; j.K = DHID;
        j.W = W_prs; j.bias = b_prs;
        j.mean_out = out + OFF_MP; j.std_out = out + OFF_SP;
        j.aload = ALOAD_PLAIN; j.epi = EPI_HEAD_STORE;
        L.mblk = TT * BB / 64; L.splitk = 1;
        gemm_kernel<<<dim3(2 * DST / 64, TT * BB / 64, 1), 256>>>(L);
    }
    // 8) finish sq + both sample outputs for all T
    sample_kernel<<<(TT * BB * DST + 255) / 256, 256>>>(out, prior_noise, post_noise);
}

// round 7
// speedup vs baseline: 1.8010x; 1.8010x over previous
#include <cuda_runtime.h>
#include <cuda_bf16.h>
#include <math.h>
#include <stdint.h>

#define TT 50
#define BB 256
#define DBEL 1024
#define DST 128
#define DACT 32
#define DHID 1024
#define DEMB 1024
#define GRU3 (3*DBEL)

// ---- output layout (tuple order: beliefs, prior_s, mp, sp, post_s, mq, sq) ----
static constexpr size_t OFF_BEL = 0;
static constexpr size_t OFF_PRS = (size_t)TT*BB*DBEL;
static constexpr size_t OFF_MP  = OFF_PRS + (size_t)TT*BB*DST;
static constexpr size_t OFF_SP  = OFF_MP  + (size_t)TT*BB*DST;
static constexpr size_t OFF_POS = OFF_SP  + (size_t)TT*BB*DST;
static constexpr size_t OFF_MQ  = OFF_POS + (size_t)TT*BB*DST;
static constexpr size_t OFF_SQ  = OFF_MQ  + (size_t)TT*BB*DST;

// ---- fp32 scratch ----
__device__ float g_x[BB*DBEL];
__device__ float g_gi[BB*GRU3];
__device__ float g_gh[BB*GRU3];
__device__ float g_belief[BB*DBEL];
__device__ float g_hq[BB*DHID];
__device__ float g_hp[(size_t)TT*BB*DHID];

// ---- bf16 hi/lo weight planes (split once per launch) ----
__device__ __nv_bfloat16 g_wsa_h[DBEL*(DST+DACT)],   g_wsa_l[DBEL*(DST+DACT)];
__device__ __nv_bfloat16 g_wih_h[GRU3*DBEL],         g_wih_l[GRU3*DBEL];
__device__ __nv_bfloat16 g_whh_h[GRU3*DBEL],         g_whh_l[GRU3*DBEL];
__device__ __nv_bfloat16 g_wpoh_h[DHID*(DBEL+DEMB)], g_wpoh_l[DHID*(DBEL+DEMB)];
__device__ __nv_bfloat16 g_wpos_h[2*DST*DHID],       g_wpos_l[2*DST*DHID];
__device__ __nv_bfloat16 g_wprh_h[DHID*DBEL],        g_wprh_l[DHID*DBEL];
__device__ __nv_bfloat16 g_wprs_h[2*DST*DHID],       g_wprs_l[2*DST*DHID];

__device__ __forceinline__ float eluf(float x)   { return x > 0.f ? x : expm1f(x); }
__device__ __forceinline__ float splusf(float x) { return fmaxf(x, 0.f) + log1pf(expf(-fabsf(x))); }
__device__ __forceinline__ float sigf(float x)   { return 1.f / (1.f + expf(-x)); }

// ================= weight split-convert =================
__global__ void conv_kernel(const float* __restrict__ s, __nv_bfloat16* __restrict__ hi,
                            __nv_bfloat16* __restrict__ lo, int n)
{
    int i = (blockIdx.x * 256 + threadIdx.x) * 4;
    if (i >= n) return;
    float4 v = *reinterpret_cast<const float4*>(s + i);
    float vv[4] = {v.x, v.y, v.z, v.w};
    __nv_bfloat16 h[4], l[4];
#pragma unroll
    for (int j = 0; j < 4; j++) {
        h[j] = __float2bfloat16_rn(vv[j]);
        l[j] = __float2bfloat16_rn(vv[j] - __bfloat162float(h[j]));
    }
    *reinterpret_cast<__nv_bfloat162*>(hi + i)     = __halves2bfloat162(h[0], h[1]);
    *reinterpret_cast<__nv_bfloat162*>(hi + i + 2) = __halves2bfloat162(h[2], h[3]);
    *reinterpret_cast<__nv_bfloat162*>(lo + i)     = __halves2bfloat162(l[0], l[1]);
    *reinterpret_cast<__nv_bfloat162*>(lo + i + 2) = __halves2bfloat162(l[2], l[3]);
}

// ================= tensor-core GEMM =================
enum { ALOAD_PLAIN = 0, ALOAD_ELU = 1, ALOAD_STATE = 2 };
enum { EPI_BIAS = 0, EPI_BIAS_ELU = 1, EPI_ATOMIC = 2, EPI_HEAD_ATOMIC = 3, EPI_HEAD_STORE = 4 };

struct GemmJob {
    const float* A1; int lda1;
    const float* A2; int lda2;
    int K1; int K;
    const __nv_bfloat16* Wh; const __nv_bfloat16* Wl;   // [N][K] bf16 hi/lo planes
    const float* bias;
    float* out; int ldout;
    float* mean_out; float* std_out;
    const float* st_mq; const float* st_sq; const float* st_eps;
    const float* st_nt; const float* st_prev;
    int aload; int epi;
};
struct GemmLaunch { GemmJob job[2]; int mblk; int splitk; };

__device__ __forceinline__ void load_a8(const GemmJob& jb, int gm, int k, float* r)
{
    if (jb.aload == ALOAD_STATE && k < jb.K1) {
        const float nt = jb.st_nt[gm];
        const int base = gm * DST + k;
        if (jb.st_mq) {
#pragma unroll
            for (int i = 0; i < 8; i++) {
                float s = splusf(jb.st_sq[base + i]) + 0.1f;
                r[i] = (jb.st_mq[base + i] + s * jb.st_eps[base + i]) * nt;
            }
        } else {
#pragma unroll
            for (int i = 0; i < 8; i++) r[i] = jb.st_prev[base + i] * nt;
        }
        return;
    }
    const float* p;
    if (k < jb.K1) p = jb.A1 + (size_t)gm * jb.lda1 + k;
    else           p = jb.A2 + (size_t)gm * jb.lda2 + (k - jb.K1);
    float4 v0 = *reinterpret_cast<const float4*>(p);
    float4 v1 = *reinterpret_cast<const float4*>(p + 4);
    r[0] = v0.x; r[1] = v0.y; r[2] = v0.z; r[3] = v0.w;
    r[4] = v1.x; r[5] = v1.y; r[6] = v1.z; r[7] = v1.w;
    if (jb.aload == ALOAD_ELU) {
#pragma unroll
        for (int i = 0; i < 8; i++) r[i] = eluf(r[i]);
    }
}

__device__ __forceinline__ void split_pack8(const float* r, uint4& h, uint4& l)
{
    uint32_t hw[4], lw[4];
#pragma unroll
    for (int i = 0; i < 4; i++) {
        __nv_bfloat16 h0 = __float2bfloat16_rn(r[2*i]);
        __nv_bfloat16 h1 = __float2bfloat16_rn(r[2*i+1]);
        __nv_bfloat16 l0 = __float2bfloat16_rn(r[2*i]   - __bfloat162float(h0));
        __nv_bfloat16 l1 = __float2bfloat16_rn(r[2*i+1] - __bfloat162float(h1));
        __nv_bfloat162 hp = __halves2bfloat162(h0, h1);
        __nv_bfloat162 lp = __halves2bfloat162(l0, l1);
        hw[i] = *reinterpret_cast<uint32_t*>(&hp);
        lw[i] = *reinterpret_cast<uint32_t*>(&lp);
    }
    h = make_uint4(hw[0], hw[1], hw[2], hw[3]);
    l = make_uint4(lw[0], lw[1], lw[2], lw[3]);
}

__device__ __forceinline__ void ldsm4(uint32_t (&r)[4], uint32_t addr) {
    asm volatile("ldmatrix.sync.aligned.m8n8.x4.shared.b16 {%0,%1,%2,%3}, [%4];"
        : "=r"(r[0]), "=r"(r[1]), "=r"(r[2]), "=r"(r[3]) : "r"(addr));
}
__device__ __forceinline__ void ldsm2(uint32_t (&r)[2], uint32_t addr) {
    asm volatile("ldmatrix.sync.aligned.m8n8.x2.shared.b16 {%0,%1}, [%2];"
        : "=r"(r[0]), "=r"(r[1]) : "r"(addr));
}
__device__ __forceinline__ void mma16816(float (&d)[4], const uint32_t (&a)[4], const uint32_t (&b)[2]) {
    asm volatile("mma.sync.aligned.m16n8k16.row.col.f32.bf16.bf16.f32 "
        "{%0,%1,%2,%3}, {%4,%5,%6,%7}, {%8,%9}, {%0,%1,%2,%3};"
        : "+f"(d[0]), "+f"(d[1]), "+f"(d[2]), "+f"(d[3])
        : "r"(a[0]), "r"(a[1]), "r"(a[2]), "r"(a[3]), "r"(b[0]), "r"(b[1]));
}

__device__ __forceinline__ void epi_pair(const GemmJob& jb, int kc, int r, int c, float v0, float v1)
{
    switch (jb.epi) {
    case EPI_BIAS: {
        float2 o = make_float2(v0 + jb.bias[c], v1 + jb.bias[c+1]);
        *reinterpret_cast<float2*>(jb.out + (size_t)r * jb.ldout + c) = o;
    } break;
    case EPI_BIAS_ELU: {
        float2 o = make_float2(eluf(v0 + jb.bias[c]), eluf(v1 + jb.bias[c+1]));
        *reinterpret_cast<float2*>(jb.out + (size_t)r * jb.ldout + c) = o;
    } break;
    case EPI_ATOMIC: {
        float* o = jb.out + (size_t)r * jb.ldout + c;
        atomicAdd(o, v0); atomicAdd(o + 1, v1);
    } break;
    case EPI_HEAD_ATOMIC: {
        float b0 = (kc == 0) ? jb.bias[c]     : 0.f;
        float b1 = (kc == 0) ? jb.bias[c + 1] : 0.f;
        if (c < DST) {
            atomicAdd(jb.mean_out + (size_t)r * DST + c,     v0 + b0);
            atomicAdd(jb.mean_out + (size_t)r * DST + c + 1, v1 + b1);
        } else {
            atomicAdd(jb.std_out + (size_t)r * DST + (c - DST),     v0 + b0);
            atomicAdd(jb.std_out + (size_t)r * DST + (c - DST) + 1, v1 + b1);
        }
    } break;
    default: { // EPI_HEAD_STORE
        float w0 = v0 + jb.bias[c], w1 = v1 + jb.bias[c+1];
        if (c < DST) {
            jb.mean_out[(size_t)r * DST + c]     = w0;
            jb.mean_out[(size_t)r * DST + c + 1] = w1;
        } else {
            jb.std_out[(size_t)r * DST + (c - DST)]     = splusf(w0) + 0.1f;
            jb.std_out[(size_t)r * DST + (c - DST) + 1] = splusf(w1) + 0.1f;
        }
    } break;
    }
}

__global__ void __launch_bounds__(256, 1) tgemm(GemmLaunch P)
{
    const GemmJob jb = P.job[blockIdx.z];
    const int mb = blockIdx.y % P.mblk;
    const int kc = blockIdx.y / P.mblk;
    const int nb = blockIdx.x;
    const int Kc = jb.K / P.splitk;
    const int kbeg = kc * Kc;
    const int nstage = Kc >> 5;

    // [stage][plane(hi/lo)][64 rows x 40 cols]  (40 = 32 + 8 pad; rows 80B, 16B-aligned)
    __shared__ __align__(16) __nv_bfloat16 sA[2][2][64*40];
    __shared__ __align__(16) __nv_bfloat16 sB[2][2][64*40];

    const int tid  = threadIdx.x;
    const int lrow = tid >> 2;          // 0..63
    const int lk   = (tid & 3) << 3;    // 0,8,16,24
    const int gm   = mb * 64 + lrow;
    const int gn   = nb * 64 + lrow;

    const int lane = tid & 31;
    const int wid  = tid >> 5;
    const int wm = (wid >> 2) * 32;     // warp M offset (0/32)
    const int wn = (wid & 3) * 16;      // warp N offset (0..48)

    // ldmatrix lane->address mapping
    const int amat = lane >> 3, arin = lane & 7;
    const int arow = wm + ((amat & 1) << 3) + arin;   // + mf*16
    const int acol = (amat >> 1) << 3;                // + kk
    const int brin = lane & 7;
    const int bmat = (lane >> 3) & 1;

    const uint32_t aBase = (uint32_t)__cvta_generic_to_shared(&sA[0][0][0]);
    const uint32_t bBase = (uint32_t)__cvta_generic_to_shared(&sB[0][0][0]);
    const uint32_t STG = 2u * 64 * 40 * 2;   // bytes per stage (both planes)
    const uint32_t PLN = 64u * 40 * 2;       // bytes per plane

    float ra[8]; uint4 rbh, rbl;

    // prologue: stage 0
    load_a8(jb, gm, kbeg + lk, ra);
    rbh = *reinterpret_cast<const uint4*>(jb.Wh + (size_t)gn * jb.K + kbeg + lk);
    rbl = *reinterpret_cast<const uint4*>(jb.Wl + (size_t)gn * jb.K + kbeg + lk);
    {
        uint4 ah, al; split_pack8(ra, ah, al);
        *reinterpret_cast<uint4*>(&sA[0][0][lrow*40 + lk]) = ah;
        *reinterpret_cast<uint4*>(&sA[0][1][lrow*40 + lk]) = al;
        *reinterpret_cast<uint4*>(&sB[0][0][lrow*40 + lk]) = rbh;
        *reinterpret_cast<uint4*>(&sB[0][1][lrow*40 + lk]) = rbl;
    }
    __syncthreads();

    float acc[2][2][4];
#pragma unroll
    for (int i = 0; i < 2; i++)
#pragma unroll
        for (int j = 0; j < 2; j++)
#pragma unroll
            for (int q = 0; q < 4; q++) acc[i][j][q] = 0.f;

    for (int t = 0; t < nstage; t++) {
        const int cur = t & 1;
        const bool more = (t + 1 < nstage);
        if (more) {
            int k = kbeg + (t + 1) * 32 + lk;
            load_a8(jb, gm, k, ra);
            rbh = *reinterpret_cast<const uint4*>(jb.Wh + (size_t)gn * jb.K + k);
            rbl = *reinterpret_cast<const uint4*>(jb.Wl + (size_t)gn * jb.K + k);
        }
        const uint32_t aOff = aBase + cur * STG;
        const uint32_t bOff = bBase + cur * STG;
#pragma unroll
        for (int kk = 0; kk < 32; kk += 16) {
            uint32_t Ah[2][4], Al[2][4], Bh[2][2], Bl[2][2];
#pragma unroll
            for (int mf = 0; mf < 2; mf++) {
                uint32_t off = (uint32_t)(((arow + mf*16) * 40 + kk + acol) * 2);
                ldsm4(Ah[mf], aOff + off);
                ldsm4(Al[mf], aOff + PLN + off);
            }
#pragma unroll
            for (int nf = 0; nf < 2; nf++) {
                uint32_t off = (uint32_t)(((wn + nf*8 + brin) * 40 + kk + bmat*8) * 2);
                ldsm2(Bh[nf], bOff + off);
                ldsm2(Bl[nf], bOff + PLN + off);
            }
#pragma unroll
            for (int mf = 0; mf < 2; mf++)
#pragma unroll
                for (int nf = 0; nf < 2; nf++) {
                    mma16816(acc[mf][nf], Ah[mf], Bh[nf]);
                    mma16816(acc[mf][nf], Ah[mf], Bl[nf]);
                    mma16816(acc[mf][nf], Al[mf], Bh[nf]);
                }
        }
        __syncthreads();
        if (more) {
            const int nxt = cur ^ 1;
            uint4 ah, al; split_pack8(ra, ah, al);
            *reinterpret_cast<uint4*>(&sA[nxt][0][lrow*40 + lk]) = ah;
            *reinterpret_cast<uint4*>(&sA[nxt][1][lrow*40 + lk]) = al;
            *reinterpret_cast<uint4*>(&sB[nxt][0][lrow*40 + lk]) = rbh;
            *reinterpret_cast<uint4*>(&sB[nxt][1][lrow*40 + lk]) = rbl;
            __syncthreads();
        }
    }

    const int gr = lane >> 2, gc = (lane & 3) << 1;
#pragma unroll
    for (int mf = 0; mf < 2; mf++)
#pragma unroll
        for (int nf = 0; nf < 2; nf++) {
            int r = mb * 64 + wm + mf * 16 + gr;
            int c = nb * 64 + wn + nf * 8 + gc;
            epi_pair(jb, kc, r,     c, acc[mf][nf][0], acc[mf][nf][1]);
            epi_pair(jb, kc, r + 8, c, acc[mf][nf][2], acc[mf][nf][3]);
        }
}

// ---- GRU combine (vectorized x4): h = (1-z)*n + z*belief; seeds g_hq with b_poh ----
__global__ void gru_kernel(const float* __restrict__ b_poh, float* __restrict__ bel_out)
{
    int i4 = (blockIdx.x * 256 + threadIdx.x) * 4;   // over BB*DBEL
    int m = i4 >> 10, j = i4 & 1023;
    const float* gi = g_gi + (size_t)m * GRU3 + j;
    const float* gh = g_gh + (size_t)m * GRU3 + j;
    float4 gir = *reinterpret_cast<const float4*>(gi);
    float4 giz = *reinterpret_cast<const float4*>(gi + 1024);
    float4 gin = *reinterpret_cast<const float4*>(gi + 2048);
    float4 ghr = *reinterpret_cast<const float4*>(gh);
    float4 ghz = *reinterpret_cast<const float4*>(gh + 1024);
    float4 ghn = *reinterpret_cast<const float4*>(gh + 2048);
    float4 b   = *reinterpret_cast<float4*>(g_belief + i4);
    float4 h;
    {
        float r = sigf(gir.x + ghr.x), z = sigf(giz.x + ghz.x);
        h.x = (1.f - z) * tanhf(gin.x + r * ghn.x) + z * b.x;
    }
    {
        float r = sigf(gir.y + ghr.y), z = sigf(giz.y + ghz.y);
        h.y = (1.f - z) * tanhf(gin.y + r * ghn.y) + z * b.y;
    }
    {
        float r = sigf(gir.z + ghr.z), z = sigf(giz.z + ghz.z);
        h.z = (1.f - z) * tanhf(gin.z + r * ghn.z) + z * b.z;
    }
    {
        float r = sigf(gir.w + ghr.w), z = sigf(giz.w + ghz.w);
        h.w = (1.f - z) * tanhf(gin.w + r * ghn.w) + z * b.w;
    }
    *reinterpret_cast<float4*>(g_belief + i4) = h;
    *reinterpret_cast<float4*>(bel_out + i4)  = h;
    *reinterpret_cast<float4*>(g_hq + i4) = *reinterpret_cast<const float4*>(b_poh + j);
}

__global__ void init_kernel(const float* __restrict__ prev_belief, float* __restrict__ out)
{
    int idx = blockIdx.x * 256 + threadIdx.x;
    if (idx < BB * DBEL) g_belief[idx] = prev_belief[idx];
    if (idx < 2 * TT * BB * DST) out[OFF_MQ + idx] = 0.f;
}

__global__ void sample_kernel(float* __restrict__ out,
                              const float* __restrict__ ep, const float* __restrict__ eq)
{
    size_t idx = (size_t)blockIdx.x * 256 + threadIdx.x;
    if (idx >= (size_t)TT * BB * DST) return;
    out[OFF_PRS + idx] = out[OFF_MP + idx] + out[OFF_SP + idx] * ep[idx];
    float s = splusf(out[OFF_SQ + idx]) + 0.1f;
    out[OFF_SQ + idx]  = s;
    out[OFF_POS + idx] = out[OFF_MQ + idx] + s * eq[idx];
}

extern "C" void kernel_launch(void* const* d_in, const int* in_sizes, int n_in,
                              void* d_out, int out_size)
{
    (void)in_sizes; (void)n_in; (void)out_size;
    const float* prev_state   = (const float*)d_in[0];
    const float* actions      = (const float*)d_in[1];
    const float* prev_belief  = (const float*)d_in[2];
    const float* observations = (const float*)d_in[3];
    const float* nonterminals = (const float*)d_in[4];
    const float* prior_noise  = (const float*)d_in[5];
    const float* post_noise   = (const float*)d_in[6];
    const float* W_sa  = (const float*)d_in[7];
    const float* b_sa  = (const float*)d_in[8];
    const float* w_ih  = (const float*)d_in[9];
    const float* b_ih  = (const float*)d_in[10];
    const float* w_hh  = (const float*)d_in[11];
    const float* b_hh  = (const float*)d_in[12];
    const float* W_prh = (const float*)d_in[13];
    const float* b_prh = (const float*)d_in[14];
    const float* W_prs = (const float*)d_in[15];
    const float* b_prs = (const float*)d_in[16];
    const float* W_poh = (const float*)d_in[17];
    const float* b_poh = (const float*)d_in[18];
    const float* W_pos = (const float*)d_in[19];
    const float* b_pos = (const float*)d_in[20];
    float* out = (float*)d_out;

    float *px, *pgi, *pgh, *pbel, *phq, *php;
    cudaGetSymbolAddress((void**)&px,   g_x);
    cudaGetSymbolAddress((void**)&pgi,  g_gi);
    cudaGetSymbolAddress((void**)&pgh,  g_gh);
    cudaGetSymbolAddress((void**)&pbel, g_belief);
    cudaGetSymbolAddress((void**)&phq,  g_hq);
    cudaGetSymbolAddress((void**)&php,  g_hp);

    __nv_bfloat16 *wsa_h, *wsa_l, *wih_h, *wih_l, *whh_h, *whh_l,
                  *wpoh_h, *wpoh_l, *wpos_h, *wpos_l, *wprh_h, *wprh_l, *wprs_h, *wprs_l;
    cudaGetSymbolAddress((void**)&wsa_h,  g_wsa_h);  cudaGetSymbolAddress((void**)&wsa_l,  g_wsa_l);
    cudaGetSymbolAddress((void**)&wih_h,  g_wih_h);  cudaGetSymbolAddress((void**)&wih_l,  g_wih_l);
    cudaGetSymbolAddress((void**)&whh_h,  g_whh_h);  cudaGetSymbolAddress((void**)&whh_l,  g_whh_l);
    cudaGetSymbolAddress((void**)&wpoh_h, g_wpoh_h); cudaGetSymbolAddress((void**)&wpoh_l, g_wpoh_l);
    cudaGetSymbolAddress((void**)&wpos_h, g_wpos_h); cudaGetSymbolAddress((void**)&wpos_l, g_wpos_l);
    cudaGetSymbolAddress((void**)&wprh_h, g_wprh_h); cudaGetSymbolAddress((void**)&wprh_l, g_wprh_l);
    cudaGetSymbolAddress((void**)&wprs_h, g_wprs_h); cudaGetSymbolAddress((void**)&wprs_l, g_wprs_l);

    auto conv = [](const float* s, __nv_bfloat16* h, __nv_bfloat16* l, int n) {
        conv_kernel<<<(n / 4 + 255) / 256, 256>>>(s, h, l, n);
    };
    conv(W_sa,  wsa_h,  wsa_l,  DBEL * (DST + DACT));
    conv(w_ih,  wih_h,  wih_l,  GRU3 * DBEL);
    conv(w_hh,  whh_h,  whh_l,  GRU3 * DBEL);
    conv(W_poh, wpoh_h, wpoh_l, DHID * (DBEL + DEMB));
    conv(W_pos, wpos_h, wpos_l, 2 * DST * DHID);
    conv(W_prh, wprh_h, wprh_l, DHID * DBEL);
    conv(W_prs, wprs_h, wprs_l, 2 * DST * DHID);

    init_kernel<<<(2 * TT * BB * DST + 255) / 256, 256>>>(prev_belief, out);

    for (int t = 0; t < TT; t++) {
        // 1) x = elu([state*nt, a_t] @ W_sa^T + b_sa), state fused from prev mq/sq/eps
        {
            GemmLaunch L = {};
            GemmJob& j = L.job[0];
            j.A2 = actions + (size_t)t * BB * DACT; j.lda2 = DACT;
            j.K1 = DST; j.K = DST + DACT;
            j.Wh = wsa_h; j.Wl = wsa_l; j.bias = b_sa;
            j.out = px; j.ldout = DBEL;
            j.st_nt = nonterminals + (size_t)t * BB;
            if (t == 0) { j.st_prev = prev_state; j.st_mq = nullptr; }
            else {
                j.st_mq  = out + OFF_MQ + (size_t)(t - 1) * BB * DST;
                j.st_sq  = out + OFF_SQ + (size_t)(t - 1) * BB * DST;
                j.st_eps = post_noise + (size_t)(t - 1) * BB * DST;
            }
            j.aload = ALOAD_STATE; j.epi = EPI_BIAS_ELU;
            L.mblk = 4; L.splitk = 1;
            tgemm<<<dim3(DBEL / 64, 4, 1), 256>>>(L);
        }
        // 2) gi = x @ w_ih^T + b_ih ; gh = belief @ w_hh^T + b_hh
        {
            GemmLaunch L = {};
            GemmJob& a = L.job[0];
            a.A1 = px; a.lda1 = DBEL; a.K1 = DBEL; a.K = DBEL;
            a.Wh = wih_h; a.Wl = wih_l; a.bias = b_ih; a.out = pgi; a.ldout = GRU3;
            a.aload = ALOAD_PLAIN; a.epi = EPI_BIAS;
            GemmJob& b = L.job[1];
            b.A1 = pbel; b.lda1 = DBEL; b.K1 = DBEL; b.K = DBEL;
            b.Wh = whh_h; b.Wl = whh_l; b.bias = b_hh; b.out = pgh; b.ldout = GRU3;
            b.aload = ALOAD_PLAIN; b.epi = EPI_BIAS;
            L.mblk = 4; L.splitk = 1;
            tgemm<<<dim3(GRU3 / 64, 4, 2), 256>>>(L);
        }
        // 3) GRU combine
        gru_kernel<<<BB * DBEL / 1024, 256>>>(b_poh, out + OFF_BEL + (size_t)t * BB * DBEL);
        // 4) hq_raw += [h, obs_t] @ W_poh^T   (split-K=2, atomic; bias pre-seeded)
        {
            GemmLaunch L = {};
            GemmJob& j = L.job[0];
            j.A1 = pbel; j.lda1 = DBEL; j.K1 = DBEL;
            j.A2 = observations + (size_t)t * BB * DEMB; j.lda2 = DEMB;
            j.K = DBEL + DEMB;
            j.Wh = wpoh_h; j.Wl = wpoh_l; j.out = phq; j.ldout = DHID;
            j.aload = ALOAD_PLAIN; j.epi = EPI_ATOMIC;
            L.mblk = 4; L.splitk = 2;
            tgemm<<<dim3(DHID / 64, 4 * 2, 1), 256>>>(L);
        }
        // 5) posterior head: elu(hq_raw) @ W_pos^T + b_pos -> mq, sq_raw (atomic, split-K=8)
        {
            GemmLaunch L = {};
            GemmJob& j = L.job[0];
            j.A1 = phq; j.lda1 = DHID; j.K1 = DHID; j.K = DHID;
            j.Wh = wpos_h; j.Wl = wpos_l; j.bias = b_pos;
            j.mean_out = out + OFF_MQ + (size_t)t * BB * DST;
            j.std_out  = out + OFF_SQ + (size_t)t * BB * DST;
            j.aload = ALOAD_ELU; j.epi = EPI_HEAD_ATOMIC;
            L.mblk = 4; L.splitk = 8;
            tgemm<<<dim3(2 * DST / 64, 4 * 8, 1), 256>>>(L);
        }
    }

    // 6) batched prior hidden: hp = elu(beliefs @ W_prh^T + b_prh), M = 12800
    {
        GemmLaunch L = {};
        GemmJob& j = L.job[0];
        j.A1 = out + OFF_BEL; j.lda1 = DBEL; j.K1 = DBEL; j.K = DBEL;
        j.Wh = wprh_h; j.Wl = wprh_l; j.bias = b_prh; j.out = php; j.ldout = DHID;
        j.aload = ALOAD_PLAIN; j.epi = EPI_BIAS_ELU;
        L.mblk = TT * BB / 64; L.splitk = 1;
        tgemm<<<dim3(DHID / 64, TT * BB / 64, 1), 256>>>(L);
    }
    // 7) batched prior head: hp @ W_prs^T + b_prs -> mp, sp
    {
        GemmLaunch L = {};
        GemmJob& j = L.job[0];
        j.A1 = php; j.lda1 = DHID; j.K1 = DHID; j.K = DHID;
        j.Wh = wprs_h; j.Wl = wprs_l; j.bias = b_prs;
        j.mean_out = out + OFF_MP; j.std_out = out + OFF_SP;
        j.aload = ALOAD_PLAIN; j.epi = EPI_HEAD_STORE;
        L.mblk = TT * BB / 64; L.splitk = 1;
        tgemm<<<dim3(2 * DST / 64, TT * BB / 64, 1), 256>>>(L);
    }
    // 8) samples
    sample_kernel<<<(TT * BB * DST + 255) / 256, 256>>>(out, prior_noise, post_noise);
}